// round 1
// baseline (speedup 1.0000x reference)
#include <cuda_runtime.h>
#include <cuda_fp16.h>
#include <cstdint>

// Problem constants
#define M_TOKENS   2048      // 4 * 512
#define IN_FEAT    2048
#define OUT_FEAT   2048
#define TILE_B     16
#define C_BLOCKS   128       // IN_FEAT / 16
#define R_BLOCKS   128       // OUT_FEAT / 16
#define K_BLOCKS   32        // C * 0.25

// Scratch (allocation-free rule: __device__ globals)
// x packed fp16, fragment-linear: [c (128)][token_group (128)][lane (32)][8 halves]
__device__ __half g_xh[(size_t)C_BLOCKS * (M_TOKENS / 16) * 32 * 8];   // 8 MB
// values packed fp16, B-fragment-linear: [r][k][ntile (2)][lane (32)][4 halves]
__device__ __half g_vh[(size_t)R_BLOCKS * K_BLOCKS * 2 * 32 * 4];      // 2 MB

// ---------------------------------------------------------------------------
// Kernel 0: pack x (fp32 [m][feat]) -> g_xh fp16 fragment layout
// For token t (0..15 within group), feature j (0..15 within block c):
//   lane = (t&7)*4 + ((j>>1)&3), pair = (t>>3) + 2*(j>>3), half = j&1
// matching mma.m16n8k16 A-fragment {a0,a1,a2,a3} register order.
// ---------------------------------------------------------------------------
__global__ void pack_x_kernel(const float* __restrict__ x) {
    int idx = blockIdx.x * blockDim.x + threadIdx.x;      // 2048*1024 threads
    if (idx >= M_TOKENS * (IN_FEAT / 2)) return;
    int m    = idx >> 10;          // token
    int rrem = idx & 1023;
    int c    = rrem >> 3;          // col block
    int jp   = rrem & 7;           // feature pair (j = 2*jp)
    float2 v = *(const float2*)(x + (size_t)m * IN_FEAT + c * TILE_B + jp * 2);
    int tg   = m >> 4;
    int t    = m & 15;
    int lane = (t & 7) * 4 + (jp & 3);
    int pair = (t >> 3) + 2 * (jp >> 2);
    __half2 h = __floats2half2_rn(v.x, v.y);
    size_t off = ((((size_t)c * (M_TOKENS / 16) + tg) * 32 + lane) * 8) + pair * 2;
    *(__half2*)(g_xh + off) = h;
}

// ---------------------------------------------------------------------------
// Kernel 0b: pack values (fp32 [r][k][i][j]) -> g_vh fp16 B-fragment layout.
// B matrix is (row=j, col=i): lane holds b0=(2q,i),(2q+1,i) ; b1=(2q+8,i),(2q+9,i)
// with q = lane&3, i = (lane>>2) + ntile*8.
// ---------------------------------------------------------------------------
__global__ void pack_v_kernel(const float* __restrict__ values) {
    int idx = blockIdx.x * blockDim.x + threadIdx.x;      // 262144 threads
    if (idx >= R_BLOCKS * K_BLOCKS * 2 * 32) return;
    int lane = idx & 31;
    int nt   = (idx >> 5) & 1;
    int k    = (idx >> 6) & 31;
    int r    = idx >> 11;
    int q    = lane & 3;
    int i    = (lane >> 2) + nt * 8;
    const float* vp = values + (((size_t)r * K_BLOCKS + k) * TILE_B + i) * TILE_B;
    float2 p0 = *(const float2*)(vp + 2 * q);
    float2 p1 = *(const float2*)(vp + 2 * q + 8);
    __half2 h0 = __floats2half2_rn(p0.x, p0.y);
    __half2 h1 = __floats2half2_rn(p1.x, p1.y);
    __half2* dst = (__half2*)(g_vh + (size_t)idx * 4);
    dst[0] = h0;
    dst[1] = h1;
}

// ---------------------------------------------------------------------------
// cp.async helpers
// ---------------------------------------------------------------------------
__device__ __forceinline__ void cp_async16(uint32_t saddr, const void* gaddr) {
    asm volatile("cp.async.cg.shared.global [%0], [%1], 16;\n"
                 :: "r"(saddr), "l"(gaddr));
}
__device__ __forceinline__ void cp_commit() {
    asm volatile("cp.async.commit_group;\n");
}
template <int N>
__device__ __forceinline__ void cp_wait() {
    asm volatile("cp.async.wait_group %0;\n" :: "n"(N));
}

__device__ __forceinline__ void mma16816(float* c, const uint4& a, const uint2& b) {
    asm volatile(
        "mma.sync.aligned.m16n8k16.row.col.f32.f16.f16.f32 "
        "{%0,%1,%2,%3}, {%4,%5,%6,%7}, {%8,%9}, {%0,%1,%2,%3};\n"
        : "+f"(c[0]), "+f"(c[1]), "+f"(c[2]), "+f"(c[3])
        : "r"(a.x), "r"(a.y), "r"(a.z), "r"(a.w), "r"(b.x), "r"(b.y));
}

// ---------------------------------------------------------------------------
// Main kernel: CTA = (token tile of 128, one output block-row r).
// grid (16, 128), block 128 (4 warps). Warp w covers token groups 2w, 2w+1.
// values[r] (16 KB fp16, fragment order) resident in smem; A slabs (4 KB,
// contiguous gather thanks to pack layout) double-buffered via cp.async.
// ---------------------------------------------------------------------------
__global__ __launch_bounds__(128)
void cms_main_kernel(const int* __restrict__ col_indices,
                     const float* __restrict__ bias,
                     float* __restrict__ out) {
    __shared__ __align__(16) __half sV[K_BLOCKS * 2 * 32 * 4];  // 16 KB
    __shared__ __align__(16) __half sA[2][8 * 32 * 8];          // 2 x 4 KB
    __shared__ int s_col[K_BLOCKS];

    const int bx  = blockIdx.x;       // token tile 0..15
    const int r   = blockIdx.y;       // 0..127
    const int tid = threadIdx.x;

    if (tid < K_BLOCKS) s_col[tid] = col_indices[r * K_BLOCKS + tid];
    __syncthreads();

    const uint32_t sv_base = (uint32_t)__cvta_generic_to_shared(sV);
    const uint32_t sa_base = (uint32_t)__cvta_generic_to_shared(&sA[0][0]);

    // Load values[r]: 16 KB contiguous, 8 chunks of 16B per thread.
    {
        const __half* gv = g_vh + (size_t)r * (K_BLOCKS * 2 * 32 * 4);
        #pragma unroll
        for (int i = 0; i < 8; i++) {
            int chunk = i * 128 + tid;
            cp_async16(sv_base + chunk * 16, gv + chunk * 8);
        }
    }
    // Prefetch A slab for k=0: 4 KB contiguous (2 chunks per thread).
    {
        int c0 = s_col[0];
        const __half* ga = g_xh + (((size_t)c0 * (M_TOKENS / 16)) + bx * 8) * 256;
        cp_async16(sa_base + tid * 16,              ga + tid * 8);
        cp_async16(sa_base + 2048 + tid * 16,       ga + (tid + 128) * 8);
    }
    cp_commit();

    float acc[16];
    #pragma unroll
    for (int i = 0; i < 16; i++) acc[i] = 0.0f;

    const int w    = tid >> 5;
    const int lane = tid & 31;

    for (int k = 0; k < K_BLOCKS; k++) {
        __syncthreads();   // prev compute done before overwriting next buffer
        if (k < K_BLOCKS - 1) {
            int cn = s_col[k + 1];
            const __half* ga = g_xh + (((size_t)cn * (M_TOKENS / 16)) + bx * 8) * 256;
            uint32_t sb = sa_base + ((k + 1) & 1) * 4096;
            cp_async16(sb + tid * 16,        ga + tid * 8);
            cp_async16(sb + 2048 + tid * 16, ga + (tid + 128) * 8);
            cp_commit();
            cp_wait<1>();
        } else {
            cp_wait<0>();
        }
        __syncthreads();

        const int buf = k & 1;
        uint4 a0 = *(const uint4*)&sA[buf][((w * 2 + 0) * 32 + lane) * 8];
        uint4 a1 = *(const uint4*)&sA[buf][((w * 2 + 1) * 32 + lane) * 8];
        uint2 b0 = *(const uint2*)&sV[((k * 2 + 0) * 32 + lane) * 4];
        uint2 b1 = *(const uint2*)&sV[((k * 2 + 1) * 32 + lane) * 4];

        mma16816(acc + 0,  a0, b0);
        mma16816(acc + 4,  a0, b1);
        mma16816(acc + 8,  a1, b0);
        mma16816(acc + 12, a1, b1);
    }

    // Epilogue: C fragment (c0,c1)@(row=g, col=2q..2q+1), (c2,c3)@(row=g+8)
    const int g = lane >> 2;
    const int q = lane & 3;
    #pragma unroll
    for (int mt = 0; mt < 2; mt++) {
        int token0 = bx * 128 + (w * 2 + mt) * 16;
        #pragma unroll
        for (int nt = 0; nt < 2; nt++) {
            int f = r * TILE_B + nt * 8 + q * 2;
            float bv0 = bias[f];
            float bv1 = bias[f + 1];
            const float* a = acc + (mt * 2 + nt) * 4;
            float* o0 = out + (size_t)(token0 + g) * OUT_FEAT + f;
            o0[0] = a[0] + bv0;
            o0[1] = a[1] + bv1;
            float* o1 = out + (size_t)(token0 + g + 8) * OUT_FEAT + f;
            o1[0] = a[2] + bv0;
            o1[1] = a[3] + bv1;
        }
    }
}

// ---------------------------------------------------------------------------
extern "C" void kernel_launch(void* const* d_in, const int* in_sizes, int n_in,
                              void* d_out, int out_size) {
    const float* x      = (const float*)d_in[0];
    const float* values = (const float*)d_in[1];
    const int*   col    = (const int*)d_in[2];
    const float* bias   = (const float*)d_in[3];
    float*       out    = (float*)d_out;

    (void)in_sizes; (void)n_in; (void)out_size;

    pack_x_kernel<<<(M_TOKENS * (IN_FEAT / 2) + 255) / 256, 256>>>(x);
    pack_v_kernel<<<(R_BLOCKS * K_BLOCKS * 2 * 32 + 255) / 256, 256>>>(values);
    cms_main_kernel<<<dim3(M_TOKENS / 128, R_BLOCKS), 128>>>(col, bias, out);
}

// round 2
// speedup vs baseline: 1.1139x; 1.1139x over previous
#include <cuda_runtime.h>
#include <cuda_fp16.h>
#include <cstdint>

// Problem constants
#define M_TOKENS   2048      // 4 * 512
#define IN_FEAT    2048
#define OUT_FEAT   2048
#define TILE_B     16
#define C_BLOCKS   128
#define R_BLOCKS   128
#define K_BLOCKS   32

// Scratch (allocation-free rule: __device__ globals)
// x packed fp16, fragment-linear: [c (128)][token_group (128)][lane (32)][8 halves]
__device__ __half g_xh[(size_t)C_BLOCKS * (M_TOKENS / 16) * 32 * 8];   // 8 MB
// values packed fp16, B-fragment-linear: [r][k][ntile (2)][lane (32)][4 halves]
__device__ __half g_vh[(size_t)R_BLOCKS * K_BLOCKS * 2 * 32 * 4];      // 2 MB

// ---------------------------------------------------------------------------
// Kernel 0: pack x -> fragment layout. One thread per 16B output fragment row:
// 4 scattered 8B loads (32B-sector friendly), 1 coalesced 16B store.
// Inverse map: for output (c, tg, lane, p):  t = (p&1)*8 + (lane>>2),
//   jp = (p>>1)*4 + (lane&3);  reads x[tg*16+t][c*16 + 2*jp .. +1].
// ---------------------------------------------------------------------------
__global__ __launch_bounds__(256)
void pack_x_kernel(const float* __restrict__ x) {
    int idx = blockIdx.x * blockDim.x + threadIdx.x;   // 128*128*32 = 524288
    int lane = idx & 31;
    int tg   = (idx >> 5) & 127;
    int c    = idx >> 12;

    const float* row = x + (size_t)(tg * 16) * IN_FEAT + c * TILE_B;
    __half2 h[4];
    #pragma unroll
    for (int p = 0; p < 4; p++) {
        int m_off = (p & 1) * 8 + (lane >> 2);
        int jp    = (p >> 1) * 4 + (lane & 3);
        float2 v  = *(const float2*)(row + (size_t)m_off * IN_FEAT + jp * 2);
        h[p] = __floats2half2_rn(v.x, v.y);
    }
    *(uint4*)(g_xh + (((size_t)c * 128 + tg) * 32 + lane) * 8) =
        *reinterpret_cast<uint4*>(h);
}

// ---------------------------------------------------------------------------
// Kernel 0b: pack values -> B-fragment layout (16B store per thread).
// ---------------------------------------------------------------------------
__global__ __launch_bounds__(256)
void pack_v_kernel(const float* __restrict__ values) {
    int idx = blockIdx.x * blockDim.x + threadIdx.x;   // 262144
    if (idx >= R_BLOCKS * K_BLOCKS * 2 * 32) return;
    int lane = idx & 31;
    int nt   = (idx >> 5) & 1;
    int k    = (idx >> 6) & 31;
    int r    = idx >> 11;
    int q    = lane & 3;
    int i    = (lane >> 2) + nt * 8;
    const float* vp = values + (((size_t)r * K_BLOCKS + k) * TILE_B + i) * TILE_B;
    float2 p0 = *(const float2*)(vp + 2 * q);
    float2 p1 = *(const float2*)(vp + 2 * q + 8);
    __half2 h[2];
    h[0] = __floats2half2_rn(p0.x, p0.y);
    h[1] = __floats2half2_rn(p1.x, p1.y);
    *(uint2*)(g_vh + (size_t)idx * 4) = *reinterpret_cast<uint2*>(h);
}

// ---------------------------------------------------------------------------
__device__ __forceinline__ void cp_async16(uint32_t saddr, const void* gaddr) {
    asm volatile("cp.async.cg.shared.global [%0], [%1], 16;\n"
                 :: "r"(saddr), "l"(gaddr));
}
__device__ __forceinline__ void cp_commit() {
    asm volatile("cp.async.commit_group;\n");
}
template <int N>
__device__ __forceinline__ void cp_wait() {
    asm volatile("cp.async.wait_group %0;\n" :: "n"(N));
}

__device__ __forceinline__ void mma16816(float* c, const uint4& a, const uint2& b) {
    asm volatile(
        "mma.sync.aligned.m16n8k16.row.col.f32.f16.f16.f32 "
        "{%0,%1,%2,%3}, {%4,%5,%6,%7}, {%8,%9}, {%0,%1,%2,%3};\n"
        : "+f"(c[0]), "+f"(c[1]), "+f"(c[2]), "+f"(c[3])
        : "r"(a.x), "r"(a.y), "r"(a.z), "r"(a.w), "r"(b.x), "r"(b.y));
}

// ---------------------------------------------------------------------------
// Main kernel: CTA = (256-token tile, one output block-row r).
// grid (8, 128), block 256 (8 warps). Warp w -> token groups 2w, 2w+1.
// values[r] (16 KB) resident in smem; A slabs (8 KB) in a 3-stage cp.async
// ring, one __syncthreads per k-iter, prefetch distance 2.
// ---------------------------------------------------------------------------
#define STAGES 3
#define SLAB_HALVES (16 * 32 * 8)    // 8 KB

__global__ __launch_bounds__(256)
void cms_main_kernel(const int* __restrict__ col_indices,
                     const float* __restrict__ bias,
                     float* __restrict__ out) {
    __shared__ __align__(16) __half sV[K_BLOCKS * 2 * 32 * 4];        // 16 KB
    __shared__ __align__(16) __half sA[STAGES][SLAB_HALVES];          // 24 KB
    __shared__ int s_col[K_BLOCKS];

    const int bx  = blockIdx.x;       // token tile 0..7 (256 tokens each)
    const int r   = blockIdx.y;
    const int tid = threadIdx.x;

    if (tid < K_BLOCKS) s_col[tid] = col_indices[r * K_BLOCKS + tid];
    __syncthreads();

    const uint32_t sv_base = (uint32_t)__cvta_generic_to_shared(sV);
    const uint32_t sa_base = (uint32_t)__cvta_generic_to_shared(&sA[0][0]);

    // Group 0: V (16 KB) + A slab 0 (8 KB). Group 1: A slab 1.
    {
        const __half* gv = g_vh + (size_t)r * (K_BLOCKS * 2 * 32 * 4);
        #pragma unroll
        for (int i = 0; i < 4; i++) {
            int chunk = i * 256 + tid;
            cp_async16(sv_base + chunk * 16, gv + chunk * 8);
        }
        const __half* ga0 = g_xh + ((size_t)s_col[0] * 128 + bx * 16) * 256;
        cp_async16(sa_base + tid * 16,        ga0 + tid * 8);
        cp_async16(sa_base + 4096 + tid * 16, ga0 + (tid + 256) * 8);
        cp_commit();
        const __half* ga1 = g_xh + ((size_t)s_col[1] * 128 + bx * 16) * 256;
        uint32_t sb1 = sa_base + SLAB_HALVES * 2;  // bytes = halves*2
        cp_async16(sb1 + tid * 16,        ga1 + tid * 8);
        cp_async16(sb1 + 4096 + tid * 16, ga1 + (tid + 256) * 8);
        cp_commit();
    }

    float acc[16];
    #pragma unroll
    for (int i = 0; i < 16; i++) acc[i] = 0.0f;

    const int w    = tid >> 5;
    const int lane = tid & 31;

    for (int k = 0; k < K_BLOCKS; k++) {
        if (k < K_BLOCKS - 1) cp_wait<1>(); else cp_wait<0>();
        __syncthreads();   // slab k visible to all; frees buf (k-1)%3 for reuse

        if (k + 2 < K_BLOCKS) {
            const __half* ga = g_xh + ((size_t)s_col[k + 2] * 128 + bx * 16) * 256;
            uint32_t sb = sa_base + ((k + 2) % STAGES) * (SLAB_HALVES * 2);
            cp_async16(sb + tid * 16,        ga + tid * 8);
            cp_async16(sb + 4096 + tid * 16, ga + (tid + 256) * 8);
            cp_commit();
        }

        const __half* Ab = sA[k % STAGES];
        uint4 a0 = *(const uint4*)&Ab[((w * 2 + 0) * 32 + lane) * 8];
        uint4 a1 = *(const uint4*)&Ab[((w * 2 + 1) * 32 + lane) * 8];
        uint2 b0 = *(const uint2*)&sV[((k * 2 + 0) * 32 + lane) * 4];
        uint2 b1 = *(const uint2*)&sV[((k * 2 + 1) * 32 + lane) * 4];

        mma16816(acc + 0,  a0, b0);
        mma16816(acc + 4,  a0, b1);
        mma16816(acc + 8,  a1, b0);
        mma16816(acc + 12, a1, b1);
    }

    // Epilogue
    const int g = lane >> 2;
    const int q = lane & 3;
    #pragma unroll
    for (int mt = 0; mt < 2; mt++) {
        int token0 = bx * 256 + (w * 2 + mt) * 16;
        #pragma unroll
        for (int nt = 0; nt < 2; nt++) {
            int f = r * TILE_B + nt * 8 + q * 2;
            float bv0 = bias[f];
            float bv1 = bias[f + 1];
            const float* a = acc + (mt * 2 + nt) * 4;
            float* o0 = out + (size_t)(token0 + g) * OUT_FEAT + f;
            o0[0] = a[0] + bv0;
            o0[1] = a[1] + bv1;
            float* o1 = out + (size_t)(token0 + g + 8) * OUT_FEAT + f;
            o1[0] = a[2] + bv0;
            o1[1] = a[3] + bv1;
        }
    }
}

// ---------------------------------------------------------------------------
extern "C" void kernel_launch(void* const* d_in, const int* in_sizes, int n_in,
                              void* d_out, int out_size) {
    const float* x      = (const float*)d_in[0];
    const float* values = (const float*)d_in[1];
    const int*   col    = (const int*)d_in[2];
    const float* bias   = (const float*)d_in[3];
    float*       out    = (float*)d_out;

    (void)in_sizes; (void)n_in; (void)out_size;

    pack_x_kernel<<<(C_BLOCKS * 128 * 32) / 256, 256>>>(x);
    pack_v_kernel<<<(R_BLOCKS * K_BLOCKS * 2 * 32) / 256, 256>>>(values);
    cms_main_kernel<<<dim3(M_TOKENS / 256, R_BLOCKS), 256>>>(col, bias, out);
}